// round 12
// baseline (speedup 1.0000x reference)
#include <cuda_runtime.h>
#include <math.h>

#define GRID_N 256
#define KS 15
#define RAD 7

__global__ void __launch_bounds__(128)
latent_lookup_kernel(
    const float* __restrict__ q,        // [B,2]
    const float* __restrict__ temp,     // [1]
    const float* __restrict__ idx2d,    // [256,256,2]
    const float* __restrict__ rm2d,     // [256,256]
    const float* __restrict__ spacing,  // [2]
    int B,
    float* __restrict__ out)            // [2,B]
{
    const int gwarp = (int)((blockIdx.x * blockDim.x + threadIdx.x) >> 5);
    const int lane  = threadIdx.x & 31;
    if (gwarp >= B) return;

    // ---- phase 1: scalar loads (first L2 round trip) ----
    const float2 qv = __ldg(&((const float2*)q)[gwarp]);
    const float2 og = __ldg(&((const float2*)idx2d)[0]);
    const float2 sp = __ldg(&((const float2*)spacing)[0]);
    const float  tv = __ldg(&temp[0]);

    const float qx = qv.x, qy = qv.y;

    // ---- phase 2: voxel/cell indices (exact rn division + rintf = jnp) ----
    const float rpx = (qx - og.x) / sp.x;
    const float rpy = (qy - og.y) / sp.y;
    int vx = (int)rintf(rpx);
    int vy = (int)rintf(rpy);
    vx = min(max(vx, RAD), GRID_N - 1 - RAD);   // never binds on valid data
    vy = min(max(vy, RAD), GRID_N - 1 - RAD);
    int fx = (int)floorf(rpx);                  // hard 2x2 cell corner
    int fy = (int)floorf(rpy);
    fx = min(max(fx, 0), GRID_N - 2);
    fy = min(max(fy, 0), GRID_N - 2);

    // ---- phase 3: issue ALL dependent loads back-to-back (second L2 round
    //      trip; everything below runs in its shadow) ----
    const int isY = (lane >> 4) & 1;
    const int hl  = lane & 15;
    const float* rowp = rm2d + ((vx - RAD) << 8) + (vy - RAD) + min(hl, 14);
    float m[8];
    #pragma unroll
    for (int r = 0; r < 8; r++) {
        const int row = min(2 * r + isY, 14);    // folds away for r < 7
        m[r] = __ldg(rowp + (row << 8));
    }
    const int  l3   = lane & 3;
    const bool isYc = (l3 >= 2);
    const int  cc   = isYc ? (fy + (l3 & 1)) : (fx + (l3 & 1));
    const float gvl = __ldg(&idx2d[isYc ? (2 * cc + 1) : (2 * GRID_N * cc)]);

    // ---- phase 4: SOFT exp weights (MUFU; no loads needed) ----
    //   ev: lanes 0..14 = ex, lane 15 = 0, lanes 16..30 = ey, lane 31 = 0
    const float invt = __fdividef(1.0f, tv + 1e-8f);
    float ev;
    {
        const int   c = (isY ? vy : vx) + hl - RAD;                  // in [0,255]
        const float n = isY ? (og.y + sp.y * (float)c) : (og.x + sp.x * (float)c);
        const float d = (isY ? qy : qx) - n;
        ev = (hl == 15) ? 0.0f : __expf(-(d * d) * invt);
    }
    const float eyc = __shfl_sync(0xffffffffu, ev, 16 + hl);  // 0 for phantom col

    // ---- phase 5: HARD, bit-exact fp32 sq_dist over 2x2 corners (verified R6-R11) ----
    const float qn = __fadd_rn(__fmul_rn(qx, qx), __fmul_rn(qy, qy));
    const float ix = __shfl_sync(0xffffffffu, gvl, lane >> 1);        // gx[fx+i]
    const float iy = __shfl_sync(0xffffffffu, gvl, 2 + (lane & 1));   // gy[fy+j]
    unsigned key  = 0xFF800000u;  // mapped(+inf)
    int      flat = 0;
    {
        const float inn = __fadd_rn(__fmul_rn(ix, ix), __fmul_rn(iy, iy));
        const float dot = __fmaf_rn(qy, iy, __fmul_rn(qx, ix));
        const float dd  = __fsub_rn(__fadd_rn(qn, inn), __fmul_rn(2.0f, dot));
        const unsigned fb = __float_as_uint(dd);
        const unsigned k2 = fb ^ ((((int)fb) >> 31) | 0x80000000u);
        if (lane < 4) {
            key  = k2;
            flat = ((fx + (lane >> 1)) << 8) + (fy + (lane & 1));
        }
    }
    const unsigned mn   = __reduce_min_sync(0xffffffffu, key);
    const unsigned bal  = __ballot_sync(0xffffffffu, key == mn);
    const int  bestFlat = __shfl_sync(0xffffffffu, flat, __ffs(bal) - 1);
    const float hard = __ldg(&rm2d[bestFlat]);   // consumed only at final store

    // ---- phase 6: weighted sum (m[] lands here at the latest) ----
    float ws = 0.0f;
    #pragma unroll
    for (int r = 0; r < 8; r++) {
        const float exr = __shfl_sync(0xffffffffu, ev, 2 * r + isY);
        ws = __fmaf_rn(exr, eyc * m[r], ws);
    }

    // ---- phase 7: reductions ----
    float red = ev;
    #pragma unroll
    for (int off = 8; off; off >>= 1)
        red += __shfl_xor_sync(0xffffffffu, red, off);   // sex | sey per half
    #pragma unroll
    for (int off = 16; off; off >>= 1)
        ws += __shfl_xor_sync(0xffffffffu, ws, off);
    const float sey = __shfl_sync(0xffffffffu, red, 16);

    if (lane == 0) {
        out[gwarp]     = hard;                         // row 0
        out[B + gwarp] = __fdividef(ws, red * sey);    // row 1 (red = sex here)
    }
}

extern "C" void kernel_launch(void* const* d_in, const int* in_sizes, int n_in,
                              void* d_out, int out_size)
{
    const float* q       = (const float*)d_in[0];
    const float* temp    = (const float*)d_in[1];
    // d_in[2] indices_db, d_in[3] relevant_metrics: unused
    const float* idx2d   = (const float*)d_in[4];
    const float* rm2d    = (const float*)d_in[5];
    const float* spacing = (const float*)d_in[6];

    const int B = in_sizes[0] / 2;
    const int threads = 128;
    const int blocks  = (B * 32 + threads - 1) / threads;
    latent_lookup_kernel<<<blocks, threads>>>(q, temp, idx2d, rm2d, spacing, B, (float*)d_out);
}

// round 13
// speedup vs baseline: 1.0337x; 1.0337x over previous
#include <cuda_runtime.h>
#include <math.h>

#define GRID_N 256
#define KS 15
#define RAD 7

__global__ void __launch_bounds__(64)
latent_lookup_kernel(
    const float* __restrict__ q,        // [B,2]
    const float* __restrict__ temp,     // [1]
    const float* __restrict__ idx2d,    // [256,256,2]
    const float* __restrict__ rm2d,     // [256,256]
    const float* __restrict__ spacing,  // [2]
    int B,
    float* __restrict__ out)            // [2,B]
{
    const int gwarp = (int)((blockIdx.x * blockDim.x + threadIdx.x) >> 5);
    const int lane  = threadIdx.x & 31;
    if (gwarp >= B) return;

    // ---- phase 1: scalar loads (first L2 round trip) ----
    const float2 qv = __ldg(&((const float2*)q)[gwarp]);
    const float2 og = __ldg(&((const float2*)idx2d)[0]);
    const float2 sp = __ldg(&((const float2*)spacing)[0]);
    const float  tv = __ldg(&temp[0]);

    const float qx = qv.x, qy = qv.y;

    // ---- phase 2: voxel/cell indices (exact rn division + rintf = jnp) ----
    const float rpx = (qx - og.x) / sp.x;
    const float rpy = (qy - og.y) / sp.y;
    int vx = (int)rintf(rpx);
    int vy = (int)rintf(rpy);
    vx = min(max(vx, RAD), GRID_N - 1 - RAD);   // never binds on valid data
    vy = min(max(vy, RAD), GRID_N - 1 - RAD);
    int fx = (int)floorf(rpx);                  // hard 2x2 cell corner
    int fy = (int)floorf(rpy);
    fx = min(max(fx, 0), GRID_N - 2);
    fy = min(max(fy, 0), GRID_N - 2);

    // ---- phase 3: issue ALL dependent loads back-to-back (second L2 round
    //      trip; everything below runs in its shadow) ----
    const int isY = (lane >> 4) & 1;
    const int hl  = lane & 15;
    const float* rowp = rm2d + ((vx - RAD) << 8) + (vy - RAD) + min(hl, 14);
    float m[8];
    #pragma unroll
    for (int r = 0; r < 8; r++) {
        const int row = min(2 * r + isY, 14);    // folds away for r < 7
        m[r] = __ldg(rowp + (row << 8));
    }
    const int  l3   = lane & 3;
    const bool isYc = (l3 >= 2);
    const int  cc   = isYc ? (fy + (l3 & 1)) : (fx + (l3 & 1));
    const float gvl = __ldg(&idx2d[isYc ? (2 * cc + 1) : (2 * GRID_N * cc)]);

    // ---- phase 4: SOFT exp weights (MUFU; no loads needed) ----
    //   ev: lanes 0..14 = ex, lane 15 = 0, lanes 16..30 = ey, lane 31 = 0
    const float invt = __fdividef(1.0f, tv + 1e-8f);
    float ev;
    {
        const int   c = (isY ? vy : vx) + hl - RAD;                  // in [0,255]
        const float n = isY ? (og.y + sp.y * (float)c) : (og.x + sp.x * (float)c);
        const float d = (isY ? qy : qx) - n;
        ev = (hl == 15) ? 0.0f : __expf(-(d * d) * invt);
    }
    const float eyc = __shfl_sync(0xffffffffu, ev, 16 + hl);  // 0 for phantom col

    // ---- phase 5: HARD, bit-exact fp32 sq_dist over 2x2 corners (verified R6-R12) ----
    const float qn = __fadd_rn(__fmul_rn(qx, qx), __fmul_rn(qy, qy));
    const float ix = __shfl_sync(0xffffffffu, gvl, lane >> 1);        // gx[fx+i]
    const float iy = __shfl_sync(0xffffffffu, gvl, 2 + (lane & 1));   // gy[fy+j]
    unsigned key  = 0xFF800000u;  // mapped(+inf)
    int      flat = 0;
    {
        const float inn = __fadd_rn(__fmul_rn(ix, ix), __fmul_rn(iy, iy));
        const float dot = __fmaf_rn(qy, iy, __fmul_rn(qx, ix));
        const float dd  = __fsub_rn(__fadd_rn(qn, inn), __fmul_rn(2.0f, dot));
        const unsigned fb = __float_as_uint(dd);
        const unsigned k2 = fb ^ ((((int)fb) >> 31) | 0x80000000u);
        if (lane < 4) {
            key  = k2;
            flat = ((fx + (lane >> 1)) << 8) + (fy + (lane & 1));
        }
    }
    const unsigned mn   = __reduce_min_sync(0xffffffffu, key);
    const unsigned bal  = __ballot_sync(0xffffffffu, key == mn);
    const int  bestFlat = __shfl_sync(0xffffffffu, flat, __ffs(bal) - 1);
    const float hard = __ldg(&rm2d[bestFlat]);   // consumed only at the store

    // ---- phase 6: weighted sum (m[] lands here at the latest) ----
    float ws = 0.0f;
    #pragma unroll
    for (int r = 0; r < 8; r++) {
        const float exr = __shfl_sync(0xffffffffu, ev, 2 * r + isY);
        ws = __fmaf_rn(exr, eyc * m[r], ws);
    }

    // ---- phase 7: reductions ----
    float red = ev;
    #pragma unroll
    for (int off = 8; off; off >>= 1)
        red += __shfl_xor_sync(0xffffffffu, red, off);   // sex | sey per half
    #pragma unroll
    for (int off = 16; off; off >>= 1)
        ws += __shfl_xor_sync(0xffffffffu, ws, off);

    // ---- phase 8: parallel stores: lane 0 -> hard, lane 16 -> soft ----
    const float sex = __shfl_sync(0xffffffffu, red, 0);   // lanes 16+: need sex
    if (lane == 0) {
        out[gwarp] = hard;                                // row 0
    } else if (lane == 16) {
        // red on lane 16 == sey; ws is warp-uniform after reduction
        out[B + gwarp] = __fdividef(ws, sex * red);       // row 1
    }
}

extern "C" void kernel_launch(void* const* d_in, const int* in_sizes, int n_in,
                              void* d_out, int out_size)
{
    const float* q       = (const float*)d_in[0];
    const float* temp    = (const float*)d_in[1];
    // d_in[2] indices_db, d_in[3] relevant_metrics: unused
    const float* idx2d   = (const float*)d_in[4];
    const float* rm2d    = (const float*)d_in[5];
    const float* spacing = (const float*)d_in[6];

    const int B = in_sizes[0] / 2;
    const int threads = 64;                  // 2 warps/block: finer dispatch interleave
    const int blocks  = (B * 32 + threads - 1) / threads;
    latent_lookup_kernel<<<blocks, threads>>>(q, temp, idx2d, rm2d, spacing, B, (float*)d_out);
}

// round 14
// speedup vs baseline: 1.0386x; 1.0048x over previous
#include <cuda_runtime.h>
#include <math.h>

#define GRID_N 256
#define KS 15
#define RAD 7

__global__ void __launch_bounds__(128)
latent_lookup_kernel(
    const float* __restrict__ q,        // [B,2]
    const float* __restrict__ temp,     // [1]
    const float* __restrict__ idx2d,    // [256,256,2]
    const float* __restrict__ rm2d,     // [256,256]
    const float* __restrict__ spacing,  // [2]
    int B,
    float* __restrict__ out)            // [2,B]
{
    const int gwarp = (int)((blockIdx.x * blockDim.x + threadIdx.x) >> 5);
    const int lane  = threadIdx.x & 31;
    if (gwarp >= B) return;

    // ---- phase 1: scalar loads (first dependent round trip) ----
    const float2 qv = __ldg(&((const float2*)q)[gwarp]);
    const float2 og = __ldg(&((const float2*)idx2d)[0]);
    const float2 sp = __ldg(&((const float2*)spacing)[0]);
    const float  tv = __ldg(&temp[0]);

    const float qx = qv.x, qy = qv.y;

    // ---- phase 2: voxel/cell indices (exact rn division + rintf = jnp) ----
    const float rpx = (qx - og.x) / sp.x;
    const float rpy = (qy - og.y) / sp.y;
    int vx = (int)rintf(rpx);
    int vy = (int)rintf(rpy);
    vx = min(max(vx, RAD), GRID_N - 1 - RAD);   // never binds on valid data
    vy = min(max(vy, RAD), GRID_N - 1 - RAD);
    int fx = (int)floorf(rpx);                  // hard 2x2 cell corner
    int fy = (int)floorf(rpy);
    fx = min(max(fx, 0), GRID_N - 2);
    fy = min(max(fy, 0), GRID_N - 2);

    // ---- phase 3: issue ALL dependent loads back-to-back (second round
    //      trip; phases 4-5 execute in its shadow) ----
    const int isY = (lane >> 4) & 1;
    const int hl  = lane & 15;
    const float* rowp = rm2d + ((vx - RAD) << 8) + (vy - RAD) + min(hl, 14);
    float m[8];
    #pragma unroll
    for (int r = 0; r < 8; r++) {
        const int row = min(2 * r + isY, 14);    // folds away for r < 7
        m[r] = __ldg(rowp + (row << 8));
    }
    const int  l3   = lane & 3;
    const bool isYc = (l3 >= 2);
    const int  cc   = isYc ? (fy + (l3 & 1)) : (fx + (l3 & 1));
    const float gvl = __ldg(&idx2d[isYc ? (2 * cc + 1) : (2 * GRID_N * cc)]);

    // ---- phase 4: SOFT exp weights (separable; MUFU only) ----
    //   ev: lanes 0..14 = ex, lane 15 = 0, lanes 16..30 = ey, lane 31 = 0
    const float invt = __fdividef(1.0f, tv + 1e-8f);
    float ev;
    {
        const int   c = (isY ? vy : vx) + hl - RAD;                  // in [0,255]
        const float n = isY ? (og.y + sp.y * (float)c) : (og.x + sp.x * (float)c);
        const float d = (isY ? qy : qx) - n;
        ev = (hl == 15) ? 0.0f : __expf(-(d * d) * invt);
    }
    const float eyc = __shfl_sync(0xffffffffu, ev, 16 + hl);  // 0 for phantom col

    // ---- phase 5: HARD, bit-exact fp32 sq_dist over 2x2 corners
    //      (replicates reference lowering exactly; verified R1-R13) ----
    const float qn = __fadd_rn(__fmul_rn(qx, qx), __fmul_rn(qy, qy));
    const float ix = __shfl_sync(0xffffffffu, gvl, lane >> 1);        // gx[fx+i]
    const float iy = __shfl_sync(0xffffffffu, gvl, 2 + (lane & 1));   // gy[fy+j]
    unsigned key  = 0xFF800000u;  // mapped(+inf)
    int      flat = 0;
    {
        const float inn = __fadd_rn(__fmul_rn(ix, ix), __fmul_rn(iy, iy));
        const float dot = __fmaf_rn(qy, iy, __fmul_rn(qx, ix));
        const float dd  = __fsub_rn(__fadd_rn(qn, inn), __fmul_rn(2.0f, dot));
        const unsigned fb = __float_as_uint(dd);
        const unsigned k2 = fb ^ ((((int)fb) >> 31) | 0x80000000u);   // monotone
        if (lane < 4) {
            key  = k2;
            flat = ((fx + (lane >> 1)) << 8) + (fy + (lane & 1));
        }
    }
    const unsigned mn   = __reduce_min_sync(0xffffffffu, key);
    const unsigned bal  = __ballot_sync(0xffffffffu, key == mn);      // lowest tied
    const int  bestFlat = __shfl_sync(0xffffffffu, flat, __ffs(bal) - 1);
    const float hard = __ldg(&rm2d[bestFlat]);   // consumed only at the store

    // ---- phase 6: weighted sum (m[] lands here at the latest) ----
    float ws = 0.0f;
    #pragma unroll
    for (int r = 0; r < 8; r++) {
        const float exr = __shfl_sync(0xffffffffu, ev, 2 * r + isY);
        ws = __fmaf_rn(exr, eyc * m[r], ws);
    }

    // ---- phase 7: reductions ----
    float red = ev;
    #pragma unroll
    for (int off = 8; off; off >>= 1)
        red += __shfl_xor_sync(0xffffffffu, red, off);   // sex | sey per half
    #pragma unroll
    for (int off = 16; off; off >>= 1)
        ws += __shfl_xor_sync(0xffffffffu, ws, off);

    // ---- phase 8: parallel stores: lane 0 -> hard, lane 16 -> soft ----
    const float sex = __shfl_sync(0xffffffffu, red, 0);
    if (lane == 0) {
        out[gwarp] = hard;                                // row 0
    } else if (lane == 16) {
        // red on lane 16 == sey; ws is warp-uniform after reduction
        out[B + gwarp] = __fdividef(ws, sex * red);       // row 1
    }
}

extern "C" void kernel_launch(void* const* d_in, const int* in_sizes, int n_in,
                              void* d_out, int out_size)
{
    const float* q       = (const float*)d_in[0];
    const float* temp    = (const float*)d_in[1];
    // d_in[2] indices_db, d_in[3] relevant_metrics: unused (window math replaces them)
    const float* idx2d   = (const float*)d_in[4];
    const float* rm2d    = (const float*)d_in[5];
    const float* spacing = (const float*)d_in[6];

    const int B = in_sizes[0] / 2;
    const int threads = 128;
    const int blocks  = (B * 32 + threads - 1) / threads;
    latent_lookup_kernel<<<blocks, threads>>>(q, temp, idx2d, rm2d, spacing, B, (float*)d_out);
}